// round 2
// baseline (speedup 1.0000x reference)
#include <cuda_runtime.h>

// GAE backward scan, round 2: deepen MLP to fix latency-bound DRAM (42% -> target 70%+).
// rewards: [T, B] f32, values: [T, B] f32, out: [T-1, B] f32
// delta[t] = r[t] + GAMMA*v[t+1] - v[t],  adv[t] = delta[t] + GL*adv[t+1]
// One thread per column. Unroll-by-16 with all 32 loads front-batched
// (MLP_p1 ~= 32 per thread, under per-warp outstanding-LDG cap ~55).
// Streaming cache hints: every byte touched exactly once.

#define T_LEN 1024
#define B_COLS 32768
#define TM1 1023           // output rows (t = 0 .. 1022)
#define GAMMA 0.99f
#define GL (0.99f * 0.95f)
#define UNROLL 16

__global__ __launch_bounds__(128) void gae_kernel(
    const float* __restrict__ rewards,
    const float* __restrict__ values,
    float* __restrict__ out)
{
    const int b = blockIdx.x * blockDim.x + threadIdx.x;

    const float* r = rewards + b;
    const float* v = values + b;
    float* o = out + b;

    float adv = 0.0f;
    float v_next = __ldcs(v + (size_t)TM1 * B_COLS);

    int t = TM1 - 1;  // 1022

    // Peel 7 so the remaining 1016 is not divisible by 16; 1016 = 63*16 + 8.
    // Instead peel so remainder fits: 1023 total iters (t=1022..0).
    // 1023 = 63*16 + 15. Peel 15 first.
    #pragma unroll
    for (int i = 0; i < 15; ++i) {
        const size_t idx = (size_t)t * B_COLS;
        const float rt = __ldcs(r + idx);
        const float vt = __ldcs(v + idx);
        const float delta = fmaf(GAMMA, v_next, rt) - vt;
        adv = fmaf(GL, adv, delta);
        __stcs(o + idx, adv);
        v_next = vt;
        --t;
    }

    // Main loop: t goes 1007 .. 0 in blocks of 16 (63 blocks).
    for (; t >= UNROLL - 1; t -= UNROLL) {
        float rt[UNROLL], vt[UNROLL];
        // Front-batch all 32 loads (independent of the adv chain).
        #pragma unroll
        for (int i = 0; i < UNROLL; ++i) {
            const size_t idx = (size_t)(t - i) * B_COLS;
            rt[i] = __ldcs(r + idx);
            vt[i] = __ldcs(v + idx);
        }
        #pragma unroll
        for (int i = 0; i < UNROLL; ++i) {
            const float delta = fmaf(GAMMA, v_next, rt[i]) - vt[i];
            adv = fmaf(GL, adv, delta);
            __stcs(o + (size_t)(t - i) * B_COLS, adv);
            v_next = vt[i];
        }
    }
}

extern "C" void kernel_launch(void* const* d_in, const int* in_sizes, int n_in,
                              void* d_out, int out_size) {
    const float* rewards = (const float*)d_in[0];
    const float* values  = (const float*)d_in[1];
    float* out = (float*)d_out;

    const int threads = 128;
    const int blocks = B_COLS / threads;  // 256, exactly one wave on 148 SMs
    gae_kernel<<<blocks, threads>>>(rewards, values, out);
}

// round 3
// speedup vs baseline: 1.6054x; 1.6054x over previous
#include <cuda_runtime.h>

// GAE backward scan, round 3: chunked linear-scan with decoupled lookback.
// adv[t] = delta[t] + GL*adv[t+1],  delta[t] = r[t] + GAMMA*v[t+1] - v[t]
// 16 time-chunks x 256 column-groups = 4096 blocks (16384 warps) vs 1024 before.
// Each block: local scan (carry 0) into 64 regs, publish chunk-sum C_k,
// combine predecessors' C_j with weights gl^(64m) (depth-1 sync), fixup, store.

#define B_COLS 32768
#define TM1 1023            // output rows t = 0 .. 1022
#define GAMMA 0.99f
#define GL (0.99f * 0.95f)
#define NCHUNK 16
#define RMAX 64             // rows per chunk (last chunk: 63 valid)
#define GBLK 256            // column groups (B_COLS / 128)

__device__ float g_scratch[NCHUNK * B_COLS];  // C_k per (chunk, column)
__device__ int   g_flags[NCHUNK * GBLK];      // publish flags
__device__ int   g_ticket;                     // ordered tile assignment

__global__ void reset_kernel() {
    int i = blockIdx.x * blockDim.x + threadIdx.x;
    if (i < NCHUNK * GBLK) g_flags[i] = 0;
    if (i == 0) g_ticket = 0;
}

__global__ __launch_bounds__(128) void gae_chunk_kernel(
    const float* __restrict__ rewards,
    const float* __restrict__ values,
    float* __restrict__ out)
{
    __shared__ int s_ticket;
    if (threadIdx.x == 0) s_ticket = atomicAdd(&g_ticket, 1);
    __syncthreads();
    const int ticket = s_ticket;
    const int k  = ticket >> 8;          // chunk index 0..15 (0 = highest t)
    const int gx = ticket & 255;         // column group
    const int c  = gx * 128 + threadIdx.x;
    const int t_hi = (TM1 - 1) - RMAX * k;   // 1022 - 64k

    const float* r = rewards + c;
    const float* v = values + c;
    float* o = out + c;

    // ---- local backward scan (carry-in = 0), 64 rows, batched loads ----
    float local[RMAX];
    float acc = 0.0f;
    float v_next = __ldcs(v + (t_hi + 1) * B_COLS);

    #pragma unroll
    for (int g0 = 0; g0 < RMAX; g0 += 8) {
        float rt[8], vt[8];
        #pragma unroll
        for (int i = 0; i < 8; ++i) {
            const int t = t_hi - (g0 + i);
            if (t >= 0) {                 // only last chunk's tail is invalid
                rt[i] = __ldcs(r + t * B_COLS);
                vt[i] = __ldcs(v + t * B_COLS);
            } else { rt[i] = 0.0f; vt[i] = 0.0f; }
        }
        #pragma unroll
        for (int i = 0; i < 8; ++i) {
            const float delta = fmaf(GAMMA, v_next, rt[i]) - vt[i];
            acc = fmaf(GL, acc, delta);
            local[g0 + i] = acc;
            v_next = vt[i];
        }
    }

    // ---- publish chunk-sum C_k (invalid tail only in k=15, which has no consumers) ----
    if (k < NCHUNK - 1) {
        g_scratch[k * B_COLS + c] = local[RMAX - 1];
        __threadfence();
        __syncthreads();
        if (threadIdx.x == 0) atomicExch(&g_flags[k * GBLK + gx], 1);
    }

    // ---- lookback: A = sum_{j<k} C_j * gl^(64*(k-1-j)) ----
    float A = 0.0f;
    if (k > 0) {
        if (threadIdx.x < k) {  // thread j spins on predecessor j's flag
            while (atomicAdd(&g_flags[threadIdx.x * GBLK + gx], 0) == 0) {}
        }
        __syncthreads();

        // gl^64 via 6 squarings (matches fp32 closely; exactness not needed at 1e-3 tol)
        const float g2 = GL * GL, g4 = g2 * g2, g8 = g4 * g4;
        const float g16 = g8 * g8, g32 = g16 * g16, gl64 = g32 * g32;

        float w = 1.0f;
        for (int j = k - 1; j >= 0; --j) {
            const float Cj = __ldcg(&g_scratch[j * B_COLS + c]);
            A = fmaf(Cj, w, A);
            w *= gl64;
        }
    }

    // ---- fixup + store: adv[t_hi - i] = local[i] + A * gl^(i+1) ----
    float Ai = A;
    #pragma unroll
    for (int i = 0; i < RMAX; ++i) {
        const int t = t_hi - i;
        Ai *= GL;
        if (t >= 0) __stcs(o + t * B_COLS, local[i] + Ai);
    }
}

extern "C" void kernel_launch(void* const* d_in, const int* in_sizes, int n_in,
                              void* d_out, int out_size) {
    const float* rewards = (const float*)d_in[0];
    const float* values  = (const float*)d_in[1];
    float* out = (float*)d_out;

    reset_kernel<<<16, 256>>>();
    gae_chunk_kernel<<<NCHUNK * GBLK, 128>>>(rewards, values, out);
}